// round 2
// baseline (speedup 1.0000x reference)
#include <cuda_runtime.h>

// ---------------- problem constants ----------------
constexpr int N_USERS   = 29858;
constexpr int N_ITEMS   = 40981;
constexpr int N_TOT     = 70839;          // N_USERS + N_ITEMS
constexpr int D         = 64;
constexpr int F         = 512;
constexpr int N_LAYERS  = 3;
constexpr int NU_ELEMS  = N_USERS * D;    // 1910912 (div by 4)
constexpr int FD        = F * D;          // 32768
constexpr int NTOT4     = N_TOT * D / 4;  // 1133424

constexpr int K1_BLOCKS = 148;
constexpr int K1_ROWS   = (N_TOT + K1_BLOCKS - 1) / K1_BLOCKS;  // 479

constexpr int K3_ROWS   = 256;            // rows per block
constexpr int K3_FC     = 64;             // f-chunk
constexpr int K3_VSTRIDE= 65;             // padded smem stride (bank-conflict free)
constexpr int K3_SMEM   = (K3_FC * D + K3_ROWS * K3_VSTRIDE) * 4;  // 82944 bytes

// ---------------- scratch (static device globals; no allocation) -------------
__device__ float g_ego[N_TOT * D];
__device__ float g_acc[N_TOT * D];
__device__ float g_part[K1_BLOCKS * FD];
__device__ float g_w[FD];

// ---------------- packed f32x2 helpers ----------------
__device__ __forceinline__ unsigned long long ffma2(unsigned long long a,
                                                    unsigned long long b,
                                                    unsigned long long c) {
    unsigned long long d;
    asm("fma.rn.f32x2 %0, %1, %2, %3;" : "=l"(d) : "l"(a), "l"(b), "l"(c));
    return d;
}
__device__ __forceinline__ unsigned long long pack2(float x) {
    unsigned long long d;
    asm("mov.b64 %0, {%1, %1};" : "=l"(d) : "f"(x));
    return d;
}
__device__ __forceinline__ float2 unpack2(unsigned long long a) {
    float2 r;
    asm("mov.b64 {%0, %1}, %2;" : "=f"(r.x), "=f"(r.y) : "l"(a));
    return r;
}

// ---------------- K0: ego = concat(user,item); acc = ego ----------------
__global__ void k_init(const float* __restrict__ u, const float* __restrict__ it) {
    int i = blockIdx.x * blockDim.x + threadIdx.x;
    if (i >= NTOT4) return;
    int e = i << 2;
    float4 t;
    if (e < NU_ELEMS) t = *(const float4*)(u + e);
    else              t = *(const float4*)(it + (e - NU_ELEMS));
    *(float4*)(g_ego + e) = t;
    *(float4*)(g_acc + e) = t;
}

// ---------------- K1: per-block partial of proj = V^T @ ego ----------------
// 1024 threads, each owns an 8f x 4d register tile (f-pairs packed as f32x2).
__global__ __launch_bounds__(1024, 1) void k_gemm1(const float* __restrict__ v) {
    __shared__ float vs[4][F];   // 8 KB
    __shared__ float es[4][D];   // 1 KB

    const int tid = threadIdx.x;
    const int fg  = tid >> 4;        // 0..63  -> f0 = fg*8
    const int dg  = tid & 15;        // 0..15  -> d0 = dg*4
    const int f0  = fg << 3;
    const int d0  = dg << 2;

    unsigned long long acc[4][4];
#pragma unroll
    for (int p = 0; p < 4; p++)
#pragma unroll
        for (int j = 0; j < 4; j++) acc[p][j] = 0ull;

    const int n_start = blockIdx.x * K1_ROWS;
    int n_end = n_start + K1_ROWS;
    if (n_end > N_TOT) n_end = N_TOT;

    for (int nb = n_start; nb < n_end; nb += 4) {
        __syncthreads();
        if (tid < 512) {
            int r = tid >> 7, c = (tid & 127) << 2;
            int n = nb + r;
            float4 t = make_float4(0.f, 0.f, 0.f, 0.f);
            if (n < n_end) t = *(const float4*)(v + (size_t)n * F + c);
            *(float4*)&vs[r][c] = t;
        } else if (tid < 576) {
            int j = tid - 512;
            int r = j >> 4, c = (j & 15) << 2;
            int n = nb + r;
            float4 t = make_float4(0.f, 0.f, 0.f, 0.f);
            if (n < n_end) t = *(const float4*)(g_ego + (size_t)n * D + c);
            *(float4*)&es[r][c] = t;
        }
        __syncthreads();

#pragma unroll
        for (int r = 0; r < 4; r++) {
            float4 e = *(const float4*)&es[r][d0];
            unsigned long long e2[4] = {pack2(e.x), pack2(e.y), pack2(e.z), pack2(e.w)};
            const unsigned long long* vrow = (const unsigned long long*)&vs[r][f0];
#pragma unroll
            for (int p = 0; p < 4; p++) {
                unsigned long long v2 = vrow[p];
#pragma unroll
                for (int j = 0; j < 4; j++) acc[p][j] = ffma2(v2, e2[j], acc[p][j]);
            }
        }
    }

    // write private partial [512 x 64]
    float* pout = g_part + (size_t)blockIdx.x * FD;
#pragma unroll
    for (int p = 0; p < 4; p++) {
#pragma unroll
        for (int j = 0; j < 4; j++) {
            float2 t = unpack2(acc[p][j]);
            pout[(f0 + 2 * p)     * D + d0 + j] = t.x;
            pout[(f0 + 2 * p + 1) * D + d0 + j] = t.y;
        }
    }
}

// ---------------- K2: W = filters[k] (*) sum_b partial_b ----------------
__global__ void k_reduce(const float* __restrict__ filt) {
    int e4 = blockIdx.x * blockDim.x + threadIdx.x;   // over FD/4 = 8192
    if (e4 >= FD / 4) return;
    int e = e4 << 2;
    float sx = 0.f, sy = 0.f, sz = 0.f, sw = 0.f;
    const float* base = g_part + e;
#pragma unroll 4
    for (int b = 0; b < K1_BLOCKS; b++) {
        float4 t = *(const float4*)(base + (size_t)b * FD);
        sx += t.x; sy += t.y; sz += t.z; sw += t.w;
    }
    float sc = filt[e >> 6];   // same f for the 4 contiguous d's
    float4 o = make_float4(sx * sc, sy * sc, sz * sc, sw * sc);
    *(float4*)(g_w + e) = o;
}

// ---------------- K3: ego = V @ W ; acc += ego ----------------
// 256 threads, 256-row tile; each thread owns 8 rows x 8 cols (d-pairs as f32x2).
__global__ __launch_bounds__(256, 2) void k_gemm2(const float* __restrict__ v) {
    extern __shared__ float sm[];
    float* ws  = sm;                 // [64][64]
    float* vsb = sm + K3_FC * D;     // [256][65]

    const int tid = threadIdx.x;
    const int rg  = tid >> 3;        // 0..31
    const int dg  = tid & 7;         // 0..7
    const int d0  = dg << 3;
    const int n0  = blockIdx.x * K3_ROWS;

    unsigned long long acc[8][4];
#pragma unroll
    for (int i = 0; i < 8; i++)
#pragma unroll
        for (int j = 0; j < 4; j++) acc[i][j] = 0ull;

    for (int fc = 0; fc < F; fc += K3_FC) {
        __syncthreads();
        // stage W chunk: 64x64 floats
#pragma unroll
        for (int k = 0; k < 4; k++) {
            int j = tid + k * 256;                    // 0..1023 float4 jobs
            *(float4*)(ws + (j << 2)) = *(const float4*)(g_w + fc * D + (j << 2));
        }
        // stage v tile: 256 rows x 64 f (padded stride 65)
#pragma unroll
        for (int k = 0; k < 16; k++) {
            int j   = tid + k * 256;                  // 0..4095
            int row = j >> 4;
            int c   = (j & 15) << 2;
            int n   = n0 + row;
            float4 t = make_float4(0.f, 0.f, 0.f, 0.f);
            if (n < N_TOT) t = *(const float4*)(v + (size_t)n * F + fc + c);
            float* dst = vsb + row * K3_VSTRIDE + c;
            dst[0] = t.x; dst[1] = t.y; dst[2] = t.z; dst[3] = t.w;
        }
        __syncthreads();

#pragma unroll 4
        for (int f = 0; f < K3_FC; f++) {
            const unsigned long long* wrow = (const unsigned long long*)(ws + f * D + d0);
            unsigned long long w0 = wrow[0], w1 = wrow[1], w2 = wrow[2], w3 = wrow[3];
#pragma unroll
            for (int i = 0; i < 8; i++) {
                unsigned long long vv = pack2(vsb[(rg + 32 * i) * K3_VSTRIDE + f]);
                acc[i][0] = ffma2(vv, w0, acc[i][0]);
                acc[i][1] = ffma2(vv, w1, acc[i][1]);
                acc[i][2] = ffma2(vv, w2, acc[i][2]);
                acc[i][3] = ffma2(vv, w3, acc[i][3]);
            }
        }
    }

    // epilogue: store ego, accumulate acc
#pragma unroll
    for (int i = 0; i < 8; i++) {
        int n = n0 + rg + 32 * i;
        if (n >= N_TOT) continue;
        float* ego_p = g_ego + (size_t)n * D + d0;
        float* acc_p = g_acc + (size_t)n * D + d0;
#pragma unroll
        for (int j = 0; j < 4; j++) {
            *(unsigned long long*)(ego_p + 2 * j) = acc[i][j];
            float2 t = unpack2(acc[i][j]);
            float2 a = *(float2*)(acc_p + 2 * j);
            a.x += t.x; a.y += t.y;
            *(float2*)(acc_p + 2 * j) = a;
        }
    }
}

// ---------------- K4: out = acc / (L+1) ----------------
__global__ void k_final(float* __restrict__ out) {
    int i = blockIdx.x * blockDim.x + threadIdx.x;
    if (i >= NTOT4) return;
    int e = i << 2;
    float4 t = *(const float4*)(g_acc + e);
    t.x *= 0.25f; t.y *= 0.25f; t.z *= 0.25f; t.w *= 0.25f;
    *(float4*)(out + e) = t;
}

// ---------------- launcher ----------------
extern "C" void kernel_launch(void* const* d_in, const int* in_sizes, int n_in,
                              void* d_out, int out_size) {
    const float* user    = (const float*)d_in[0];
    const float* item    = (const float*)d_in[1];
    const float* v       = (const float*)d_in[2];
    const float* filters = (const float*)d_in[3];
    float* out = (float*)d_out;

    cudaFuncSetAttribute(k_gemm2, cudaFuncAttributeMaxDynamicSharedMemorySize, K3_SMEM);

    const int ew_blocks = (NTOT4 + 255) / 256;
    k_init<<<ew_blocks, 256>>>(user, item);

    for (int l = 0; l < N_LAYERS; l++) {
        k_gemm1<<<K1_BLOCKS, 1024>>>(v);
        k_reduce<<<FD / 4 / 256, 256>>>(filters + l * F);
        k_gemm2<<<(N_TOT + K3_ROWS - 1) / K3_ROWS, 256, K3_SMEM>>>(v);
    }

    k_final<<<ew_blocks, 256>>>(out);
}

// round 4
// speedup vs baseline: 1.2236x; 1.2236x over previous
#include <cuda_runtime.h>
#include <cuda_bf16.h>
#include <cstdint>

// ---------------- problem constants ----------------
constexpr int N_USERS  = 29858;
constexpr int N_ITEMS  = 40981;
constexpr int N_TOT    = 70839;
constexpr int D        = 64;
constexpr int F        = 512;
constexpr int N_LAYERS = 3;
constexpr int NPAD     = 70912;                 // 554 * 128, zero padded
constexpr int NU_ELEMS = N_USERS * D;
constexpr int NTOT4    = N_TOT * D / 4;

constexpr int KSPLITS  = 37;
constexpr int CH_TOT   = NPAD / 64;             // 1108 K-chunks of 64 (GEMM1)
constexpr int CH_PER_SPLIT = 30;                // 36*30 + 28 = 1108

// ---------------- scratch (static device globals; no allocation) -------------
__device__ float          g_ego[N_TOT * D];
__device__ float          g_acc[N_TOT * D];
__device__ unsigned short g_vth[(size_t)F * NPAD];   // V^T hi  [512][NPAD] bf16
__device__ unsigned short g_vtl[(size_t)F * NPAD];   // V^T lo
__device__ unsigned short g_egoth[(size_t)D * NPAD]; // ego^T hi [64][NPAD]
__device__ unsigned short g_egotl[(size_t)D * NPAD]; // ego^T lo
__device__ unsigned short g_wth[D * F];              // W^T hi [64][512]
__device__ unsigned short g_wtl[D * F];              // W^T lo
__device__ float          g_p1[KSPLITS * 4 * 128 * D]; // GEMM1 partials

// ---------------- helpers ----------------
__device__ __forceinline__ uint32_t smem_u32(const void* p) {
    uint32_t a;
    asm("{ .reg .u64 t; cvta.to.shared.u64 t, %1; cvt.u32.u64 %0, t; }"
        : "=r"(a) : "l"(p));
    return a;
}
// XOR swizzle for 128-byte rows (conflict-free ldmatrix)
__device__ __forceinline__ uint32_t swz(uint32_t o) { return o ^ ((o >> 3) & 0x70); }

// split 8 floats into hi/lo bf16 16B chunks
__device__ __forceinline__ void split8(const float* f, uint4& hi, uint4& lo) {
    unsigned int hw[4], lw[4];
#pragma unroll
    for (int i = 0; i < 4; i++) {
        __nv_bfloat16 h0 = __float2bfloat16(f[2 * i]);
        __nv_bfloat16 h1 = __float2bfloat16(f[2 * i + 1]);
        float r0 = f[2 * i]     - __bfloat162float(h0);
        float r1 = f[2 * i + 1] - __bfloat162float(h1);
        __nv_bfloat16 l0 = __float2bfloat16(r0);
        __nv_bfloat16 l1 = __float2bfloat16(r1);
        hw[i] = (unsigned)__bfloat16_as_ushort(h0) | ((unsigned)__bfloat16_as_ushort(h1) << 16);
        lw[i] = (unsigned)__bfloat16_as_ushort(l0) | ((unsigned)__bfloat16_as_ushort(l1) << 16);
    }
    hi = make_uint4(hw[0], hw[1], hw[2], hw[3]);
    lo = make_uint4(lw[0], lw[1], lw[2], lw[3]);
}

__device__ __forceinline__ void ldsm_x4(uint32_t* r, uint32_t a) {
    asm volatile("ldmatrix.sync.aligned.m8n8.x4.shared.b16 {%0,%1,%2,%3}, [%4];"
                 : "=r"(r[0]), "=r"(r[1]), "=r"(r[2]), "=r"(r[3]) : "r"(a));
}
__device__ __forceinline__ void ldsm_x2(uint32_t* r, uint32_t a) {
    asm volatile("ldmatrix.sync.aligned.m8n8.x2.shared.b16 {%0,%1}, [%2];"
                 : "=r"(r[0]), "=r"(r[1]) : "r"(a));
}
__device__ __forceinline__ void mma_bf16(float* c, const uint32_t* a, const uint32_t* b) {
    asm volatile(
        "mma.sync.aligned.m16n8k16.row.col.f32.bf16.bf16.f32 "
        "{%0,%1,%2,%3}, {%4,%5,%6,%7}, {%8,%9}, {%0,%1,%2,%3};"
        : "+f"(c[0]), "+f"(c[1]), "+f"(c[2]), "+f"(c[3])
        : "r"(a[0]), "r"(a[1]), "r"(a[2]), "r"(a[3]), "r"(b[0]), "r"(b[1]));
}

// ---------------- K0: ego = concat(user,item); acc = ego ----------------
__global__ void k_init(const float* __restrict__ u, const float* __restrict__ it) {
    int i = blockIdx.x * blockDim.x + threadIdx.x;
    if (i >= NTOT4) return;
    int e = i << 2;
    float4 t;
    if (e < NU_ELEMS) t = *(const float4*)(u + e);
    else              t = *(const float4*)(it + (e - NU_ELEMS));
    *(float4*)(g_ego + e) = t;
    *(float4*)(g_acc + e) = t;
}

// ---------------- prep: V -> V^T hi/lo bf16 (tiled transpose + split) --------
__global__ void k_prep_v(const float* __restrict__ v) {
    __shared__ float t[64][65];
    int n0 = blockIdx.x * 64;
    int f0 = blockIdx.y * 64;
    int tid = threadIdx.x;
    for (int j = tid; j < 1024; j += 256) {
        int r = j >> 4, c = (j & 15) << 2;
        int n = n0 + r;
        float4 val = make_float4(0.f, 0.f, 0.f, 0.f);
        if (n < N_TOT) val = *(const float4*)(v + (size_t)n * F + f0 + c);
        t[r][c] = val.x; t[r][c + 1] = val.y; t[r][c + 2] = val.z; t[r][c + 3] = val.w;
    }
    __syncthreads();
    for (int j = tid; j < 512; j += 256) {
        int f = j >> 3, c = (j & 7) << 3;
        float vals[8];
#pragma unroll
        for (int i = 0; i < 8; i++) vals[i] = t[c + i][f];
        uint4 hi, lo;
        split8(vals, hi, lo);
        size_t off = (size_t)(f0 + f) * NPAD + n0 + c;
        *(uint4*)(g_vth + off) = hi;
        *(uint4*)(g_vtl + off) = lo;
    }
}

// ---------------- per layer: ego -> ego^T hi/lo bf16 ----------------
__global__ void k_conv_ego() {
    __shared__ float t[64][65];
    int n0 = blockIdx.x * 64;
    int tid = threadIdx.x;
    for (int j = tid; j < 1024; j += 256) {
        int r = j >> 4, c = (j & 15) << 2;
        int n = n0 + r;
        float4 val = make_float4(0.f, 0.f, 0.f, 0.f);
        if (n < N_TOT) val = *(const float4*)(g_ego + (size_t)n * D + c);
        t[r][c] = val.x; t[r][c + 1] = val.y; t[r][c + 2] = val.z; t[r][c + 3] = val.w;
    }
    __syncthreads();
    for (int j = tid; j < 512; j += 256) {
        int d = j >> 3, c = (j & 7) << 3;
        float vals[8];
#pragma unroll
        for (int i = 0; i < 8; i++) vals[i] = t[c + i][d];
        uint4 hi, lo;
        split8(vals, hi, lo);
        size_t off = (size_t)d * NPAD + n0 + c;
        *(uint4*)(g_egoth + off) = hi;
        *(uint4*)(g_egotl + off) = lo;
    }
}

// ---------------- reduce partials, fold filters, split W^T ----------------
__global__ void k_reduce1(const float* __restrict__ filt) {
    int gid = blockIdx.x * blockDim.x + threadIdx.x;  // 32768
    int f = gid >> 6, d = gid & 63;
    int mt = f >> 7, fl = f & 127;
    float s = 0.f;
    for (int ks = 0; ks < KSPLITS; ks++)
        s += g_p1[((ks << 2) + mt) * 8192 + fl * 64 + d];
    s *= filt[f];
    __nv_bfloat16 h = __float2bfloat16(s);
    float r = s - __bfloat162float(h);
    g_wth[d * F + f] = __bfloat16_as_ushort(h);
    g_wtl[d * F + f] = __bfloat16_as_ushort(__float2bfloat16(r));
}

// ---------------- warp-MMA GEMM (both shapes) ----------------
// C[128 x 64] = A[128 x K] * B[64 x K]^T  (A,B K-major, split hi/lo bf16)
// MODE 0: A = V^T tile (g_vth/g_vtl), B = ego^T, K-split over NPAD -> g_p1 partial
// MODE 1: A = V rows converted from fp32, B = W^T, K = F=512; ego'=C, acc+=C
template <int MODE>
__global__ __launch_bounds__(256, 2) void k_gemm(const float* __restrict__ vsrc) {
    __shared__ __align__(128) unsigned short sAh[128 * 64];
    __shared__ __align__(128) unsigned short sAl[128 * 64];
    __shared__ __align__(128) unsigned short sBh[64 * 64];
    __shared__ __align__(128) unsigned short sBl[64 * 64];

    const int tid  = threadIdx.x;
    const int w    = tid >> 5;
    const int lane = tid & 31;

    int m0, c0, nc;            // m-origin, first chunk, chunk count
    if (MODE == 0) {
        int mt = blockIdx.x & 3;
        int ks = blockIdx.x >> 2;
        m0 = mt * 128;
        c0 = ks * CH_PER_SPLIT;
        nc = min(CH_PER_SPLIT, CH_TOT - c0);
    } else {
        m0 = blockIdx.x * 128;
        c0 = 0;
        nc = F / 64;           // 8
    }

    float acc[8][4];
#pragma unroll
    for (int nt = 0; nt < 8; nt++)
#pragma unroll
        for (int j = 0; j < 4; j++) acc[nt][j] = 0.f;

    const uint32_t sAh_b = smem_u32(sAh), sAl_b = smem_u32(sAl);
    const uint32_t sBh_b = smem_u32(sBh), sBl_b = smem_u32(sBl);

    // per-thread ldmatrix addresses (fixed row parts)
    const int a_row = w * 16 + (lane & 15);
    const int a_colh = (lane >> 4) * 8;           // half index within k16
    const int b_rowl = lane & 7;                  // + nt*8
    const int b_colh = ((lane >> 3) & 1) * 8;

    for (int ch = 0; ch < nc; ch++) {
        const int k0 = (c0 + ch) * 64;
        __syncthreads();
        // ---- stage A (128 x 64) hi/lo ----
        if (MODE == 0) {
            for (int j = tid; j < 1024; j += 256) {
                int row = j >> 3, ck = j & 7;
                size_t src = (size_t)(m0 + row) * NPAD + k0 + ck * 8;
                uint32_t dst = swz(row * 128 + ck * 16);
                *(uint4*)((char*)sAh + dst) = *(const uint4*)(g_vth + src);
                *(uint4*)((char*)sAl + dst) = *(const uint4*)(g_vtl + src);
            }
            for (int j = tid; j < 512; j += 256) {
                int row = j >> 3, ck = j & 7;
                size_t src = (size_t)row * NPAD + k0 + ck * 8;
                uint32_t dst = swz(row * 128 + ck * 16);
                *(uint4*)((char*)sBh + dst) = *(const uint4*)(g_egoth + src);
                *(uint4*)((char*)sBl + dst) = *(const uint4*)(g_egotl + src);
            }
        } else {
            for (int j = tid; j < 1024; j += 256) {
                int row = j >> 3, ck = j & 7;
                int m = m0 + row;
                float vals[8];
                if (m < N_TOT) {
                    const float4* p = (const float4*)(vsrc + (size_t)m * F + k0 + ck * 8);
                    float4 x0 = p[0], x1 = p[1];
                    vals[0] = x0.x; vals[1] = x0.y; vals[2] = x0.z; vals[3] = x0.w;
                    vals[4] = x1.x; vals[5] = x1.y; vals[6] = x1.z; vals[7] = x1.w;
                } else {
#pragma unroll
                    for (int i = 0; i < 8; i++) vals[i] = 0.f;
                }
                uint4 hi, lo;
                split8(vals, hi, lo);
                uint32_t dst = swz(row * 128 + ck * 16);
                *(uint4*)((char*)sAh + dst) = hi;
                *(uint4*)((char*)sAl + dst) = lo;
            }
            for (int j = tid; j < 512; j += 256) {
                int row = j >> 3, ck = j & 7;
                size_t src = (size_t)row * F + k0 + ck * 8;
                uint32_t dst = swz(row * 128 + ck * 16);
                *(uint4*)((char*)sBh + dst) = *(const uint4*)(g_wth + src);
                *(uint4*)((char*)sBl + dst) = *(const uint4*)(g_wtl + src);
            }
        }
        __syncthreads();

        // ---- 4 k16 steps ----
#pragma unroll
        for (int ks = 0; ks < 4; ks++) {
            uint32_t ah[4], al[4];
            uint32_t aoff = swz((uint32_t)(a_row * 128 + (a_colh + ks * 16) * 2));
            ldsm_x4(ah, sAh_b + aoff);
            ldsm_x4(al, sAl_b + aoff);
#pragma unroll
            for (int nt = 0; nt < 8; nt++) {
                uint32_t bh[2], bl[2];
                uint32_t boff = swz((uint32_t)((nt * 8 + b_rowl) * 128 + (b_colh + ks * 16) * 2));
                ldsm_x2(bh, sBh_b + boff);
                ldsm_x2(bl, sBl_b + boff);
                mma_bf16(acc[nt], ah, bh);
                mma_bf16(acc[nt], ah, bl);
                mma_bf16(acc[nt], al, bh);
            }
        }
    }

    // ---- epilogue ----
    const int r0 = w * 16 + (lane >> 2);          // rows r0 and r0+8
    const int ncol = 2 * (lane & 3);              // + nt*8
    if (MODE == 0) {
        float* out = g_p1 + (size_t)blockIdx.x * 8192;
#pragma unroll
        for (int nt = 0; nt < 8; nt++) {
            int n = nt * 8 + ncol;
            *(float2*)(out + r0 * 64 + n)       = make_float2(acc[nt][0], acc[nt][1]);
            *(float2*)(out + (r0 + 8) * 64 + n) = make_float2(acc[nt][2], acc[nt][3]);
        }
    } else {
#pragma unroll
        for (int half = 0; half < 2; half++) {
            int m = m0 + r0 + half * 8;
            if (m >= N_TOT) continue;
            float* ep = g_ego + (size_t)m * D;
            float* ap = g_acc + (size_t)m * D;
#pragma unroll
            for (int nt = 0; nt < 8; nt++) {
                int n = nt * 8 + ncol;
                float2 t = half ? make_float2(acc[nt][2], acc[nt][3])
                                : make_float2(acc[nt][0], acc[nt][1]);
                *(float2*)(ep + n) = t;
                float2 a = *(float2*)(ap + n);
                a.x += t.x; a.y += t.y;
                *(float2*)(ap + n) = a;
            }
        }
    }
}

// ---------------- K4: out = acc / (L+1) ----------------
__global__ void k_final(float* __restrict__ out) {
    int i = blockIdx.x * blockDim.x + threadIdx.x;
    if (i >= NTOT4) return;
    int e = i << 2;
    float4 t = *(const float4*)(g_acc + e);
    t.x *= 0.25f; t.y *= 0.25f; t.z *= 0.25f; t.w *= 0.25f;
    *(float4*)(out + e) = t;
}

// ---------------- launcher ----------------
extern "C" void kernel_launch(void* const* d_in, const int* in_sizes, int n_in,
                              void* d_out, int out_size) {
    const float* user    = (const float*)d_in[0];
    const float* item    = (const float*)d_in[1];
    const float* v       = (const float*)d_in[2];
    const float* filters = (const float*)d_in[3];
    float* out = (float*)d_out;

    const int ew_blocks = (NTOT4 + 255) / 256;
    k_init<<<ew_blocks, 256>>>(user, item);
    k_prep_v<<<dim3(NPAD / 64, F / 64), 256>>>(v);

    for (int l = 0; l < N_LAYERS; l++) {
        k_conv_ego<<<NPAD / 64, 256>>>();
        k_gemm<0><<<KSPLITS * 4, 256>>>(v);                 // proj partials
        k_reduce1<<<(F * D) / 256, 256>>>(filters + l * F); // W^T hi/lo
        k_gemm<1><<<(NPAD / 128), 256>>>(v);                // ego' = V W ; acc +=
    }

    k_final<<<ew_blocks, 256>>>(out);
}

// round 5
// speedup vs baseline: 2.8338x; 2.3160x over previous
#include <cuda_runtime.h>
#include <cuda_bf16.h>
#include <cstdint>

// ---------------- problem constants ----------------
constexpr int N_USERS  = 29858;
constexpr int N_ITEMS  = 40981;
constexpr int N_TOT    = 70839;
constexpr int D        = 64;
constexpr int F        = 512;
constexpr int N_LAYERS = 3;
constexpr int NPAD     = 70912;                 // 554 * 128, zero padded
constexpr int NU_ELEMS = N_USERS * D;
constexpr int NTOT4    = N_TOT * D / 4;

constexpr int KSPLITS      = 74;                // GEMM1 split-K (grid = 296)
constexpr int CH_TOT       = NPAD / 64;         // 1108 K-chunks of 64
constexpr int CH_PER_SPLIT = 15;                // 73*15 + 13 = 1108

// smem stage: Ah 16K | Al 16K | Bh 8K | Bl 8K = 48 KB; 2 stages = 96 KB
constexpr int A_OFF_L = 16384;
constexpr int B_OFF_H = 32768;
constexpr int B_OFF_L = 40960;
constexpr int STAGE   = 49152;
constexpr int GEMM_SMEM = 2 * STAGE + 128;

// ---------------- scratch (static device globals; no allocation) -------------
__device__ __align__(128) float          g_ego[N_TOT * D];
__device__ __align__(128) float          g_acc[N_TOT * D];
__device__ __align__(128) unsigned short g_vth[(size_t)F * NPAD];   // V^T hi [512][NPAD]
__device__ __align__(128) unsigned short g_vtl[(size_t)F * NPAD];   // V^T lo
__device__ __align__(128) unsigned short g_egoth[(size_t)D * NPAD]; // ego^T hi
__device__ __align__(128) unsigned short g_egotl[(size_t)D * NPAD]; // ego^T lo
__device__ __align__(128) unsigned short g_wth[D * F];              // W^T hi [64][512]
__device__ __align__(128) unsigned short g_wtl[D * F];              // W^T lo
__device__ __align__(128) float          g_p1[KSPLITS * 4 * 128 * D];

// ---------------- helpers ----------------
__device__ __forceinline__ uint32_t smem_u32(const void* p) {
    uint32_t a;
    asm("{ .reg .u64 t; cvta.to.shared.u64 t, %1; cvt.u32.u64 %0, t; }"
        : "=r"(a) : "l"(p));
    return a;
}
__device__ __forceinline__ uint32_t swz(uint32_t o) { return o ^ ((o >> 3) & 0x70); }

__device__ __forceinline__ void cp16(uint32_t dst, const void* src) {
    asm volatile("cp.async.cg.shared.global [%0], [%1], 16;"
                 :: "r"(dst), "l"(src) : "memory");
}
__device__ __forceinline__ void cp_commit() {
    asm volatile("cp.async.commit_group;" ::: "memory");
}
template <int N>
__device__ __forceinline__ void cp_wait() {
    asm volatile("cp.async.wait_group %0;" :: "n"(N) : "memory");
}

__device__ __forceinline__ void split8(const float* f, uint4& hi, uint4& lo) {
    unsigned int hw[4], lw[4];
#pragma unroll
    for (int i = 0; i < 4; i++) {
        __nv_bfloat16 h0 = __float2bfloat16(f[2 * i]);
        __nv_bfloat16 h1 = __float2bfloat16(f[2 * i + 1]);
        float r0 = f[2 * i]     - __bfloat162float(h0);
        float r1 = f[2 * i + 1] - __bfloat162float(h1);
        __nv_bfloat16 l0 = __float2bfloat16(r0);
        __nv_bfloat16 l1 = __float2bfloat16(r1);
        hw[i] = (unsigned)__bfloat16_as_ushort(h0) | ((unsigned)__bfloat16_as_ushort(h1) << 16);
        lw[i] = (unsigned)__bfloat16_as_ushort(l0) | ((unsigned)__bfloat16_as_ushort(l1) << 16);
    }
    hi = make_uint4(hw[0], hw[1], hw[2], hw[3]);
    lo = make_uint4(lw[0], lw[1], lw[2], lw[3]);
}

__device__ __forceinline__ void ldsm_x4(uint32_t* r, uint32_t a) {
    asm volatile("ldmatrix.sync.aligned.m8n8.x4.shared.b16 {%0,%1,%2,%3}, [%4];"
                 : "=r"(r[0]), "=r"(r[1]), "=r"(r[2]), "=r"(r[3]) : "r"(a));
}
__device__ __forceinline__ void ldsm_x4_t(uint32_t* r, uint32_t a) {
    asm volatile("ldmatrix.sync.aligned.m8n8.x4.trans.shared.b16 {%0,%1,%2,%3}, [%4];"
                 : "=r"(r[0]), "=r"(r[1]), "=r"(r[2]), "=r"(r[3]) : "r"(a));
}
__device__ __forceinline__ void ldsm_x2(uint32_t* r, uint32_t a) {
    asm volatile("ldmatrix.sync.aligned.m8n8.x2.shared.b16 {%0,%1}, [%2];"
                 : "=r"(r[0]), "=r"(r[1]) : "r"(a));
}
__device__ __forceinline__ void mma_bf16(float* c, const uint32_t* a, const uint32_t* b) {
    asm volatile(
        "mma.sync.aligned.m16n8k16.row.col.f32.bf16.bf16.f32 "
        "{%0,%1,%2,%3}, {%4,%5,%6,%7}, {%8,%9}, {%0,%1,%2,%3};"
        : "+f"(c[0]), "+f"(c[1]), "+f"(c[2]), "+f"(c[3])
        : "r"(a[0]), "r"(a[1]), "r"(a[2]), "r"(a[3]), "r"(b[0]), "r"(b[1]));
}

// ---------------- K0: ego = concat(user,item); acc = ego ----------------
__global__ void k_init(const float* __restrict__ u, const float* __restrict__ it) {
    int i = blockIdx.x * blockDim.x + threadIdx.x;
    if (i >= NTOT4) return;
    int e = i << 2;
    float4 t;
    if (e < NU_ELEMS) t = *(const float4*)(u + e);
    else              t = *(const float4*)(it + (e - NU_ELEMS));
    *(float4*)(g_ego + e) = t;
    *(float4*)(g_acc + e) = t;
}

// ---------------- prep: V -> V^T hi/lo bf16 (tiled transpose + split) --------
__global__ void k_prep_v(const float* __restrict__ v) {
    __shared__ float t[64][65];
    int n0 = blockIdx.x * 64;
    int f0 = blockIdx.y * 64;
    int tid = threadIdx.x;
    for (int j = tid; j < 1024; j += 256) {
        int r = j >> 4, c = (j & 15) << 2;
        int n = n0 + r;
        float4 val = make_float4(0.f, 0.f, 0.f, 0.f);
        if (n < N_TOT) val = *(const float4*)(v + (size_t)n * F + f0 + c);
        t[r][c] = val.x; t[r][c + 1] = val.y; t[r][c + 2] = val.z; t[r][c + 3] = val.w;
    }
    __syncthreads();
    for (int j = tid; j < 512; j += 256) {
        int f = j >> 3, c = (j & 7) << 3;
        float vals[8];
#pragma unroll
        for (int i = 0; i < 8; i++) vals[i] = t[c + i][f];
        uint4 hi, lo;
        split8(vals, hi, lo);
        size_t off = (size_t)(f0 + f) * NPAD + n0 + c;
        *(uint4*)(g_vth + off) = hi;
        *(uint4*)(g_vtl + off) = lo;
    }
}

// ---------------- per layer: ego -> ego^T hi/lo bf16 ----------------
__global__ void k_conv_ego() {
    __shared__ float t[64][65];
    int n0 = blockIdx.x * 64;
    int tid = threadIdx.x;
    for (int j = tid; j < 1024; j += 256) {
        int r = j >> 4, c = (j & 15) << 2;
        int n = n0 + r;
        float4 val = make_float4(0.f, 0.f, 0.f, 0.f);
        if (n < N_TOT) val = *(const float4*)(g_ego + (size_t)n * D + c);
        t[r][c] = val.x; t[r][c + 1] = val.y; t[r][c + 2] = val.z; t[r][c + 3] = val.w;
    }
    __syncthreads();
    for (int j = tid; j < 512; j += 256) {
        int d = j >> 3, c = (j & 7) << 3;
        float vals[8];
#pragma unroll
        for (int i = 0; i < 8; i++) vals[i] = t[c + i][d];
        uint4 hi, lo;
        split8(vals, hi, lo);
        size_t off = (size_t)d * NPAD + n0 + c;
        *(uint4*)(g_egoth + off) = hi;
        *(uint4*)(g_egotl + off) = lo;
    }
}

// ---------------- reduce partials, fold filters, split W^T ----------------
__global__ void k_reduce1(const float* __restrict__ filt) {
    int gid = blockIdx.x * blockDim.x + threadIdx.x;  // 32768
    int f = gid >> 6, d = gid & 63;
    int mt = f >> 7, fl = f & 127;
    float s = 0.f;
    for (int ks = 0; ks < KSPLITS; ks++)
        s += g_p1[((ks << 2) + mt) * 8192 + fl * 64 + d];
    s *= filt[f];
    __nv_bfloat16 h = __float2bfloat16(s);
    float r = s - __bfloat162float(h);
    g_wth[d * F + f] = __bfloat16_as_ushort(h);
    g_wtl[d * F + f] = __bfloat16_as_ushort(__float2bfloat16(r));
}

// ---------------- cp.async staging (both modes are pure copies) --------------
// MODE 0: A = V^T tile [128 f][64 n]  (rows 128B, swizzled)
//         B = ego^T   [64 d][64 n]
// MODE 1: A = At tile  [64 f][128 m] stored as 2 segs of [64 f][64 m] (rows 128B)
//         B = W^T      [64 d][64 f]
template <int MODE>
__device__ __forceinline__ void stage_issue(uint32_t sbuf, int m0, int k0, int tid) {
    if (MODE == 0) {
        for (int j = tid; j < 1024; j += 256) {
            int row = j >> 3, q = j & 7;
            size_t src = (size_t)(m0 + row) * NPAD + k0 + q * 8;
            uint32_t d = swz(row * 128 + q * 16);
            cp16(sbuf + d,           g_vth + src);
            cp16(sbuf + A_OFF_L + d, g_vtl + src);
        }
        for (int j = tid; j < 512; j += 256) {
            int row = j >> 3, q = j & 7;
            size_t src = (size_t)row * NPAD + k0 + q * 8;
            uint32_t d = swz(row * 128 + q * 16);
            cp16(sbuf + B_OFF_H + d, g_egoth + src);
            cp16(sbuf + B_OFF_L + d, g_egotl + src);
        }
    } else {
        for (int j = tid; j < 1024; j += 256) {
            int f = j >> 4, seg = (j >> 3) & 1, q = j & 7;
            size_t src = (size_t)(k0 + f) * NPAD + m0 + seg * 64 + q * 8;
            uint32_t d = seg * 8192 + swz(f * 128 + q * 16);
            cp16(sbuf + d,           g_vth + src);
            cp16(sbuf + A_OFF_L + d, g_vtl + src);
        }
        for (int j = tid; j < 512; j += 256) {
            int row = j >> 3, q = j & 7;
            size_t src = (size_t)row * F + k0 + q * 8;
            uint32_t d = swz(row * 128 + q * 16);
            cp16(sbuf + B_OFF_H + d, g_wth + src);
            cp16(sbuf + B_OFF_L + d, g_wtl + src);
        }
    }
}

// ---------------- pipelined warp-MMA GEMM ----------------
// C[128 x 64] = A[128 x K] * B[64 x K]^T, hi/lo bf16 split (3 MMA terms)
template <int MODE>
__global__ __launch_bounds__(256, 2) void k_gemm() {
    extern __shared__ char smraw[];
    uint32_t smb = smem_u32(smraw);
    const uint32_t sm0 = (smb + 127) & ~127u;

    const int tid  = threadIdx.x;
    const int w    = tid >> 5;
    const int lane = tid & 31;

    int m0, c0, nc;
    if (MODE == 0) {
        int mt = blockIdx.x & 3;
        int ks = blockIdx.x >> 2;
        m0 = mt * 128;
        c0 = ks * CH_PER_SPLIT;
        nc = min(CH_PER_SPLIT, CH_TOT - c0);
    } else {
        m0 = blockIdx.x * 128;
        c0 = 0;
        nc = F / 64;
    }

    float acc[8][4];
#pragma unroll
    for (int nt = 0; nt < 8; nt++)
#pragma unroll
        for (int j = 0; j < 4; j++) acc[nt][j] = 0.f;

    // A-fragment addressing
    const int a_row  = w * 16 + (lane & 15);          // MODE 0
    const int a_colh = (lane >> 4) * 8;
    const int f_l    = (lane & 7) | ((lane & 16) >> 1); // MODE 1 (trans)
    const int m_l    = w * 16 + (lane & 8);
    const uint32_t aseg = (uint32_t)(m_l >> 6) * 8192;
    const uint32_t am2  = (uint32_t)(m_l & 63) * 2;
    // B-fragment addressing
    const int b_rowl = lane & 7;
    const int b_colh = ((lane >> 3) & 1) * 8;

    stage_issue<MODE>(sm0, m0, (MODE == 0 ? (c0) * 64 : 0), tid);
    cp_commit();

    for (int ch = 0; ch < nc; ch++) {
        const uint32_t buf = sm0 + (uint32_t)(ch & 1) * STAGE;
        if (ch + 1 < nc) {
            stage_issue<MODE>(sm0 + (uint32_t)((ch + 1) & 1) * STAGE,
                              m0, (c0 + ch + 1) * 64, tid);
            cp_commit();
            cp_wait<1>();
        } else {
            cp_wait<0>();
        }
        __syncthreads();

        const uint32_t sAh = buf, sAl = buf + A_OFF_L;
        const uint32_t sBh = buf + B_OFF_H, sBl = buf + B_OFF_L;
#pragma unroll
        for (int ks = 0; ks < 4; ks++) {
            uint32_t ah[4], al[4];
            if (MODE == 0) {
                uint32_t ao = swz((uint32_t)(a_row * 128 + (ks * 16 + a_colh) * 2));
                ldsm_x4(ah, sAh + ao);
                ldsm_x4(al, sAl + ao);
            } else {
                uint32_t ao = aseg + swz((uint32_t)((ks * 16 + f_l) * 128) + am2);
                ldsm_x4_t(ah, sAh + ao);
                ldsm_x4_t(al, sAl + ao);
            }
#pragma unroll
            for (int nt = 0; nt < 8; nt++) {
                uint32_t bh[2], bl[2];
                uint32_t bo = swz((uint32_t)((nt * 8 + b_rowl) * 128 + (ks * 16 + b_colh) * 2));
                ldsm_x2(bh, sBh + bo);
                ldsm_x2(bl, sBl + bo);
                mma_bf16(acc[nt], ah, bh);
                mma_bf16(acc[nt], ah, bl);
                mma_bf16(acc[nt], al, bh);
            }
        }
        __syncthreads();
    }

    // ---- epilogue ----
    const int r0   = w * 16 + (lane >> 2);
    const int ncol = 2 * (lane & 3);
    if (MODE == 0) {
        float* out = g_p1 + (size_t)blockIdx.x * 8192;
#pragma unroll
        for (int nt = 0; nt < 8; nt++) {
            int n = nt * 8 + ncol;
            *(float2*)(out + r0 * 64 + n)       = make_float2(acc[nt][0], acc[nt][1]);
            *(float2*)(out + (r0 + 8) * 64 + n) = make_float2(acc[nt][2], acc[nt][3]);
        }
    } else {
#pragma unroll
        for (int half = 0; half < 2; half++) {
            int m = m0 + r0 + half * 8;
            if (m >= N_TOT) continue;
            float* ep = g_ego + (size_t)m * D;
            float* ap = g_acc + (size_t)m * D;
#pragma unroll
            for (int nt = 0; nt < 8; nt++) {
                int n = nt * 8 + ncol;
                float2 t = half ? make_float2(acc[nt][2], acc[nt][3])
                                : make_float2(acc[nt][0], acc[nt][1]);
                *(float2*)(ep + n) = t;
                float2 a = *(float2*)(ap + n);
                a.x += t.x; a.y += t.y;
                *(float2*)(ap + n) = a;
            }
        }
    }
}

// ---------------- K4: out = acc / (L+1) ----------------
__global__ void k_final(float* __restrict__ out) {
    int i = blockIdx.x * blockDim.x + threadIdx.x;
    if (i >= NTOT4) return;
    int e = i << 2;
    float4 t = *(const float4*)(g_acc + e);
    t.x *= 0.25f; t.y *= 0.25f; t.z *= 0.25f; t.w *= 0.25f;
    *(float4*)(out + e) = t;
}

// ---------------- launcher ----------------
extern "C" void kernel_launch(void* const* d_in, const int* in_sizes, int n_in,
                              void* d_out, int out_size) {
    const float* user    = (const float*)d_in[0];
    const float* item    = (const float*)d_in[1];
    const float* v       = (const float*)d_in[2];
    const float* filters = (const float*)d_in[3];
    float* out = (float*)d_out;

    cudaFuncSetAttribute(k_gemm<0>, cudaFuncAttributeMaxDynamicSharedMemorySize, GEMM_SMEM);
    cudaFuncSetAttribute(k_gemm<1>, cudaFuncAttributeMaxDynamicSharedMemorySize, GEMM_SMEM);

    const int ew_blocks = (NTOT4 + 255) / 256;
    k_init<<<ew_blocks, 256>>>(user, item);
    k_prep_v<<<dim3(NPAD / 64, F / 64), 256>>>(v);

    for (int l = 0; l < N_LAYERS; l++) {
        k_conv_ego<<<NPAD / 64, 256>>>();
        k_gemm<0><<<KSPLITS * 4, 256, GEMM_SMEM>>>();        // proj partials
        k_reduce1<<<(F * D) / 256, 256>>>(filters + l * F);  // W^T hi/lo
        k_gemm<1><<<NPAD / 128, 256, GEMM_SMEM>>>();         // ego' = V W ; acc +=
    }

    k_final<<<ew_blocks, 256>>>(out);
}

// round 6
// speedup vs baseline: 2.8559x; 1.0078x over previous
#include <cuda_runtime.h>
#include <cuda_bf16.h>
#include <cstdint>

// ---------------- problem constants ----------------
constexpr int N_USERS  = 29858;
constexpr int N_ITEMS  = 40981;
constexpr int N_TOT    = 70839;
constexpr int D        = 64;
constexpr int F        = 512;
constexpr int N_LAYERS = 3;
constexpr int NPAD     = 70912;                 // 554 * 128
constexpr int NU_ELEMS = N_USERS * D;
constexpr int NTOT4    = N_TOT * D / 4;

constexpr int KC           = 32;                // K per pipeline chunk
constexpr int CH_TOT       = NPAD / KC;         // 2216
constexpr int KSPLITS      = 74;                // GEMM1 split-K (grid 296)
constexpr int CH_PER_SPLIT = (CH_TOT + KSPLITS - 1) / KSPLITS;  // 30

// smem stage: Ah 8K | Al 8K | Bh 4K | Bl 4K = 24 KB; 4 stages = 96 KB
constexpr int A_OFF_L = 8192;
constexpr int B_OFF_H = 16384;
constexpr int B_OFF_L = 20480;
constexpr int STAGE   = 24576;
constexpr int NSTAGE  = 4;
constexpr int GEMM_SMEM = NSTAGE * STAGE + 1024;

// ---------------- scratch (static device globals; no allocation) -------------
// natural n-major layouts; padding rows [N_TOT, NPAD) stay zero (zero-init)
__device__ __align__(128) float          g_acc[N_TOT * D];
__device__ __align__(128) unsigned short g_vh[(size_t)NPAD * F];   // V hi  [n][512]
__device__ __align__(128) unsigned short g_vl[(size_t)NPAD * F];   // V lo
__device__ __align__(128) unsigned short g_eh[(size_t)NPAD * D];   // ego hi [n][64]
__device__ __align__(128) unsigned short g_el[(size_t)NPAD * D];   // ego lo
__device__ __align__(128) unsigned short g_wh[D * F];              // W^T hi [64][512]
__device__ __align__(128) unsigned short g_wl[D * F];              // W^T lo
__device__ __align__(128) float          g_p1[KSPLITS * 4 * 128 * D];

// ---------------- helpers ----------------
__device__ __forceinline__ uint32_t smem_u32(const void* p) {
    uint32_t a;
    asm("{ .reg .u64 t; cvta.to.shared.u64 t, %1; cvt.u32.u64 %0, t; }"
        : "=r"(a) : "l"(p));
    return a;
}
__device__ __forceinline__ uint32_t swz(uint32_t o) { return o ^ ((o >> 3) & 0x70); }

__device__ __forceinline__ void cp16(uint32_t dst, const void* src) {
    asm volatile("cp.async.cg.shared.global [%0], [%1], 16;"
                 :: "r"(dst), "l"(src) : "memory");
}
__device__ __forceinline__ void cp_commit() {
    asm volatile("cp.async.commit_group;" ::: "memory");
}
template <int N>
__device__ __forceinline__ void cp_wait() {
    asm volatile("cp.async.wait_group %0;" :: "n"(N) : "memory");
}

__device__ __forceinline__ void split8(const float* f, uint4& hi, uint4& lo) {
    unsigned int hw[4], lw[4];
#pragma unroll
    for (int i = 0; i < 4; i++) {
        __nv_bfloat16 h0 = __float2bfloat16(f[2 * i]);
        __nv_bfloat16 h1 = __float2bfloat16(f[2 * i + 1]);
        float r0 = f[2 * i]     - __bfloat162float(h0);
        float r1 = f[2 * i + 1] - __bfloat162float(h1);
        __nv_bfloat16 l0 = __float2bfloat16(r0);
        __nv_bfloat16 l1 = __float2bfloat16(r1);
        hw[i] = (unsigned)__bfloat16_as_ushort(h0) | ((unsigned)__bfloat16_as_ushort(h1) << 16);
        lw[i] = (unsigned)__bfloat16_as_ushort(l0) | ((unsigned)__bfloat16_as_ushort(l1) << 16);
    }
    hi = make_uint4(hw[0], hw[1], hw[2], hw[3]);
    lo = make_uint4(lw[0], lw[1], lw[2], lw[3]);
}

__device__ __forceinline__ void ldsm_x4(uint32_t* r, uint32_t a) {
    asm volatile("ldmatrix.sync.aligned.m8n8.x4.shared.b16 {%0,%1,%2,%3}, [%4];"
                 : "=r"(r[0]), "=r"(r[1]), "=r"(r[2]), "=r"(r[3]) : "r"(a));
}
__device__ __forceinline__ void ldsm_x4_t(uint32_t* r, uint32_t a) {
    asm volatile("ldmatrix.sync.aligned.m8n8.x4.trans.shared.b16 {%0,%1,%2,%3}, [%4];"
                 : "=r"(r[0]), "=r"(r[1]), "=r"(r[2]), "=r"(r[3]) : "r"(a));
}
__device__ __forceinline__ void mma_bf16(float* c, const uint32_t* a,
                                         uint32_t b0, uint32_t b1) {
    asm volatile(
        "mma.sync.aligned.m16n8k16.row.col.f32.bf16.bf16.f32 "
        "{%0,%1,%2,%3}, {%4,%5,%6,%7}, {%8,%9}, {%0,%1,%2,%3};"
        : "+f"(c[0]), "+f"(c[1]), "+f"(c[2]), "+f"(c[3])
        : "r"(a[0]), "r"(a[1]), "r"(a[2]), "r"(a[3]), "r"(b0), "r"(b1));
}

// ---------------- K0: acc = concat(user,item); ego hi/lo split ---------------
__global__ void k_init(const float* __restrict__ u, const float* __restrict__ it) {
    int i = blockIdx.x * blockDim.x + threadIdx.x;
    // zero ego padding rows [N_TOT, NPAD)
    if (i < (NPAD - N_TOT) * D / 4) {
        uint2 z = make_uint2(0u, 0u);
        *(uint2*)(g_eh + (size_t)N_TOT * D + i * 4) = z;
        *(uint2*)(g_el + (size_t)N_TOT * D + i * 4) = z;
    }
    if (i >= NTOT4) return;
    int e = i << 2;
    float4 t;
    if (e < NU_ELEMS) t = *(const float4*)(u + e);
    else              t = *(const float4*)(it + (e - NU_ELEMS));
    *(float4*)(g_acc + e) = t;
    float vals[4] = {t.x, t.y, t.z, t.w};
    unsigned int hw[2], lw[2];
#pragma unroll
    for (int p = 0; p < 2; p++) {
        __nv_bfloat16 h0 = __float2bfloat16(vals[2 * p]);
        __nv_bfloat16 h1 = __float2bfloat16(vals[2 * p + 1]);
        float r0 = vals[2 * p]     - __bfloat162float(h0);
        float r1 = vals[2 * p + 1] - __bfloat162float(h1);
        hw[p] = (unsigned)__bfloat16_as_ushort(h0) |
                ((unsigned)__bfloat16_as_ushort(h1) << 16);
        lw[p] = (unsigned)__bfloat16_as_ushort(__float2bfloat16(r0)) |
                ((unsigned)__bfloat16_as_ushort(__float2bfloat16(r1)) << 16);
    }
    *(uint2*)(g_eh + e) = make_uint2(hw[0], hw[1]);
    *(uint2*)(g_el + e) = make_uint2(lw[0], lw[1]);
}

// ---------------- prep: V fp32 -> hi/lo bf16, n-major (pure stream) ----------
__global__ void k_prep(const float* __restrict__ v) {
    size_t i = (size_t)blockIdx.x * blockDim.x + threadIdx.x;  // NPAD*F/8 jobs
    size_t e = i * 8;
    int n = (int)(e >> 9);
    uint4 hi, lo;
    if (n < N_TOT) {
        float4 x0 = *(const float4*)(v + e);
        float4 x1 = *(const float4*)(v + e + 4);
        float vals[8] = {x0.x, x0.y, x0.z, x0.w, x1.x, x1.y, x1.z, x1.w};
        split8(vals, hi, lo);
    } else {
        hi = make_uint4(0, 0, 0, 0);
        lo = make_uint4(0, 0, 0, 0);
    }
    *(uint4*)(g_vh + e) = hi;
    *(uint4*)(g_vl + e) = lo;
}

// ---------------- reduce partials, fold filters, split W^T ----------------
__global__ void k_reduce1(const float* __restrict__ filt) {
    int gid = blockIdx.x * blockDim.x + threadIdx.x;  // 32768
    int f = gid >> 6, d = gid & 63;
    int mt = f >> 7, fl = f & 127;
    float s = 0.f;
    for (int ks = 0; ks < KSPLITS; ks++)
        s += g_p1[((ks << 2) + mt) * 8192 + fl * 64 + d];
    s *= filt[f];
    __nv_bfloat16 h = __float2bfloat16(s);
    float r = s - __bfloat162float(h);
    g_wh[d * F + f] = __bfloat16_as_ushort(h);
    g_wl[d * F + f] = __bfloat16_as_ushort(__float2bfloat16(r));
}

// ---------------- cp.async staging (pure copies, both modes) -----------------
// MODE 0 (proj = V^T ego):  A = [KC n][128 f] (2 segs of 64f/128B rows)
//                           B = [KC n][64 d]  (128B rows)
// MODE 1 (ego' = V W):      A = [128 m][KC f] (64B rows)
//                           B = [64 d][KC f]  (64B rows)
template <int MODE>
__device__ __forceinline__ void stage_issue(uint32_t sbuf, int m0, int k0, int tid) {
    if (MODE == 0) {
        for (int j = tid; j < 512; j += 256) {
            int n = j >> 4, seg = (j >> 3) & 1, q = j & 7;
            size_t src = (size_t)(k0 + n) * F + m0 + seg * 64 + q * 8;
            uint32_t d = seg * 4096 + swz(n * 128 + q * 16);
            cp16(sbuf + d,           g_vh + src);
            cp16(sbuf + A_OFF_L + d, g_vl + src);
        }
        {
            int j = tid & 255;
            int n = j >> 3, q = j & 7;
            size_t src = (size_t)(k0 + n) * D + q * 8;
            uint32_t d = swz(n * 128 + q * 16);
            cp16(sbuf + B_OFF_H + d, g_eh + src);
            cp16(sbuf + B_OFF_L + d, g_el + src);
        }
    } else {
        for (int j = tid; j < 512; j += 256) {
            int m = j >> 2, q = j & 3;
            size_t src = (size_t)(m0 + m) * F + k0 + q * 8;
            uint32_t d = swz(m * 64 + q * 16);
            cp16(sbuf + d,           g_vh + src);
            cp16(sbuf + A_OFF_L + d, g_vl + src);
        }
        {
            int j = tid & 255;
            int dd = j >> 2, q = j & 3;
            size_t src = (size_t)dd * F + k0 + q * 8;
            uint32_t d = swz(dd * 64 + q * 16);
            cp16(sbuf + B_OFF_H + d, g_wh + src);
            cp16(sbuf + B_OFF_L + d, g_wl + src);
        }
    }
}

// ---------------- pipelined warp-MMA GEMM ----------------
// C[128 x 64] = A[128 x K] * B[64 x K]^T, hi/lo bf16 split (3 MMA terms)
template <int MODE>
__global__ __launch_bounds__(256, 2) void k_gemm() {
    extern __shared__ char smraw[];
    const uint32_t sm0 = (smem_u32(smraw) + 1023) & ~1023u;

    const int tid  = threadIdx.x;
    const int w    = tid >> 5;
    const int lane = tid & 31;

    int m0, c0, nc;
    if (MODE == 0) {
        int mt = blockIdx.x & 3;
        int ks = blockIdx.x >> 2;
        m0 = mt * 128;                         // f-tile origin
        c0 = ks * CH_PER_SPLIT;
        nc = min(CH_PER_SPLIT, CH_TOT - c0);
    } else {
        m0 = blockIdx.x * 128;                 // n-tile origin
        c0 = 0;
        nc = F / KC;                           // 16
    }

    float acc[8][4];
#pragma unroll
    for (int nt = 0; nt < 8; nt++)
#pragma unroll
        for (int j = 0; j < 4; j++) acc[nt][j] = 0.f;

    // fragment addressing
    // MODE 0: A trans from [n][f]; B trans from [n][d]
    const int a_k   = (lane & 7) | ((lane & 16) >> 1);      // k row (trans A)
    const uint32_t a_seg = (uint32_t)(w >> 2) * 4096;
    const uint32_t a_f2  = (uint32_t)((w * 16 + (lane & 8)) & 63) * 2;
    const int bt_k  = lane & 15;                            // k row (trans B)
    const int bt_n8 = ((lane >> 4) & 1) * 8;
    // MODE 1: A plain from [m][f]; B plain from [d][f]
    const int a_row  = w * 16 + (lane & 15);
    const int a_colh = (lane >> 4) * 8;
    const int bp_row = lane & 15;
    const int bp_k8  = ((lane >> 4) & 1) * 8;

#pragma unroll
    for (int s = 0; s < NSTAGE - 1; s++) {
        if (s < nc) stage_issue<MODE>(sm0 + s * STAGE, m0, (c0 + s) * KC, tid);
        cp_commit();
    }

    for (int ch = 0; ch < nc; ch++) {
        cp_wait<NSTAGE - 2>();
        __syncthreads();
        const int nx = ch + NSTAGE - 1;
        if (nx < nc) stage_issue<MODE>(sm0 + (nx & 3) * STAGE, m0, (c0 + nx) * KC, tid);
        cp_commit();

        const uint32_t buf = sm0 + (uint32_t)(ch & 3) * STAGE;
        const uint32_t sAh = buf, sAl = buf + A_OFF_L;
        const uint32_t sBh = buf + B_OFF_H, sBl = buf + B_OFF_L;

#pragma unroll
        for (int ks = 0; ks < KC / 16; ks++) {
            uint32_t ah[4], al[4];
            if (MODE == 0) {
                uint32_t ao = a_seg + swz((uint32_t)((ks * 16 + a_k) * 128) + a_f2);
                ldsm_x4_t(ah, sAh + ao);
                ldsm_x4_t(al, sAl + ao);
            } else {
                uint32_t ao = swz((uint32_t)(a_row * 64 + (ks * 16 + a_colh) * 2));
                ldsm_x4(ah, sAh + ao);
                ldsm_x4(al, sAl + ao);
            }
#pragma unroll
            for (int nt2 = 0; nt2 < 4; nt2++) {
                uint32_t bh[4], bl[4];
                if (MODE == 0) {
                    // trans x4: r0,r1 = b0,b1 of even tile; r2,r3 = odd tile
                    uint32_t bo = swz((uint32_t)((ks * 16 + bt_k) * 128 +
                                                 (nt2 * 16 + bt_n8) * 2));
                    ldsm_x4_t(bh, sBh + bo);
                    ldsm_x4_t(bl, sBl + bo);
                    float* cE = acc[2 * nt2];
                    float* cO = acc[2 * nt2 + 1];
                    mma_bf16(cE, ah, bh[0], bh[1]);
                    mma_bf16(cE, ah, bl[0], bl[1]);
                    mma_bf16(cE, al, bh[0], bh[1]);
                    mma_bf16(cO, ah, bh[2], bh[3]);
                    mma_bf16(cO, ah, bl[2], bl[3]);
                    mma_bf16(cO, al, bh[2], bh[3]);
                } else {
                    // plain x4: r0,r2 = even tile; r1,r3 = odd tile
                    uint32_t bo = swz((uint32_t)((nt2 * 16 + bp_row) * 64 +
                                                 (ks * 16 + bp_k8) * 2));
                    ldsm_x4(bh, sBh + bo);
                    ldsm_x4(bl, sBl + bo);
                    float* cE = acc[2 * nt2];
                    float* cO = acc[2 * nt2 + 1];
                    mma_bf16(cE, ah, bh[0], bh[2]);
                    mma_bf16(cE, ah, bl[0], bl[2]);
                    mma_bf16(cE, al, bh[0], bh[2]);
                    mma_bf16(cO, ah, bh[1], bh[3]);
                    mma_bf16(cO, ah, bl[1], bl[3]);
                    mma_bf16(cO, al, bh[1], bh[3]);
                }
            }
        }
        __syncthreads();
    }

    // ---- epilogue ----
    const int r0   = w * 16 + (lane >> 2);
    const int ncol = 2 * (lane & 3);
    if (MODE == 0) {
        float* out = g_p1 + (size_t)blockIdx.x * 8192;
#pragma unroll
        for (int nt = 0; nt < 8; nt++) {
            int n = nt * 8 + ncol;
            *(float2*)(out + r0 * 64 + n)       = make_float2(acc[nt][0], acc[nt][1]);
            *(float2*)(out + (r0 + 8) * 64 + n) = make_float2(acc[nt][2], acc[nt][3]);
        }
    } else {
#pragma unroll
        for (int half = 0; half < 2; half++) {
            int m = m0 + r0 + half * 8;
            if (m >= N_TOT) continue;
            float* ap = g_acc + (size_t)m * D;
            unsigned short* ehp = g_eh + (size_t)m * D;
            unsigned short* elp = g_el + (size_t)m * D;
#pragma unroll
            for (int nt = 0; nt < 8; nt++) {
                int n = nt * 8 + ncol;
                float cx = acc[nt][half * 2], cy = acc[nt][half * 2 + 1];
                float2 a = *(float2*)(ap + n);
                a.x += cx; a.y += cy;
                *(float2*)(ap + n) = a;
                __nv_bfloat16 hx = __float2bfloat16(cx);
                __nv_bfloat16 hy = __float2bfloat16(cy);
                float rx = cx - __bfloat162float(hx);
                float ry = cy - __bfloat162float(hy);
                unsigned int hw = (unsigned)__bfloat16_as_ushort(hx) |
                                  ((unsigned)__bfloat16_as_ushort(hy) << 16);
                unsigned int lw = (unsigned)__bfloat16_as_ushort(__float2bfloat16(rx)) |
                                  ((unsigned)__bfloat16_as_ushort(__float2bfloat16(ry)) << 16);
                *(unsigned int*)(ehp + n) = hw;
                *(unsigned int*)(elp + n) = lw;
            }
        }
    }
}

// ---------------- K4: out = acc / (L+1) ----------------
__global__ void k_final(float* __restrict__ out) {
    int i = blockIdx.x * blockDim.x + threadIdx.x;
    if (i >= NTOT4) return;
    int e = i << 2;
    float4 t = *(const float4*)(g_acc + e);
    t.x *= 0.25f; t.y *= 0.25f; t.z *= 0.25f; t.w *= 0.25f;
    *(float4*)(out + e) = t;
}

// ---------------- launcher ----------------
extern "C" void kernel_launch(void* const* d_in, const int* in_sizes, int n_in,
                              void* d_out, int out_size) {
    const float* user    = (const float*)d_in[0];
    const float* item    = (const float*)d_in[1];
    const float* v       = (const float*)d_in[2];
    const float* filters = (const float*)d_in[3];
    float* out = (float*)d_out;

    cudaFuncSetAttribute(k_gemm<0>, cudaFuncAttributeMaxDynamicSharedMemorySize, GEMM_SMEM);
    cudaFuncSetAttribute(k_gemm<1>, cudaFuncAttributeMaxDynamicSharedMemorySize, GEMM_SMEM);

    const int ew_blocks = (NTOT4 + 255) / 256;
    k_init<<<ew_blocks, 256>>>(user, item);
    k_prep<<<(int)((size_t)NPAD * F / 8 / 256), 256>>>(v);

    for (int l = 0; l < N_LAYERS; l++) {
        k_gemm<0><<<KSPLITS * 4, 256, GEMM_SMEM>>>();        // proj partials
        k_reduce1<<<(F * D) / 256, 256>>>(filters + l * F);  // W^T hi/lo
        k_gemm<1><<<NPAD / 128, 256, GEMM_SMEM>>>();         // ego' = V W ; acc+=, split
    }

    k_final<<<ew_blocks, 256>>>(out);
}